// round 4
// baseline (speedup 1.0000x reference)
#include <cuda_runtime.h>
#include <math.h>
#include <float.h>

#define BB 4
#define PP 8192
#define CC 64
#define MM 2048
#define KK 32
#define CIN 67
#define H1 128
#define Q1 64
#define NPIX (BB*MM*KK)
#define BN_EPS 1e-5f

// ---------------- scratch (device globals; no allocation allowed) ----------------
__device__ float g_featsT[(size_t)BB*PP*CC];        // (B,P,C) transposed feats
__device__ int   g_idx[(size_t)BB*MM*KK];           // KNN indices
__device__ float g_h0[(size_t)BB*MM*KK*H1];         // conv1 pre-BN
__device__ float g_f0[(size_t)BB*MM*KK*H1];         // conv2 pre-BN
__device__ float g_stats1[2*H1];
__device__ float g_stats2[2*H1];
__device__ float g_aff1[2*H1];
__device__ float g_aff2[2*H1];

// ---------------- feats transpose (B,C,P) -> (B,P,C) ----------------
__global__ void k_pre(const float* __restrict__ feats) {
    int gp = blockIdx.x * blockDim.x + threadIdx.x;   // 0..BB*PP-1
    if (gp >= BB*PP) return;
    int b = gp / PP, p = gp % PP;
    const float* src = feats + (size_t)b*CC*PP + p;
    float4* dst = (float4*)(g_featsT + (size_t)gp*CC);
#pragma unroll
    for (int c0 = 0; c0 < CC; c0 += 4) {
        float4 v;
        v.x = src[(size_t)(c0+0)*PP];
        v.y = src[(size_t)(c0+1)*PP];
        v.z = src[(size_t)(c0+2)*PP];
        v.w = src[(size_t)(c0+3)*PP];
        dst[c0 >> 2] = v;
    }
}

// ---------------- centers (exact jax linspace semantics) ----------------
__global__ void k_centers(const float* __restrict__ xyz, float* __restrict__ out) {
    int i = blockIdx.x * blockDim.x + threadIdx.x;
    if (i >= BB*MM) return;
    int b = i / MM, m = i % MM;
    int pc;
    if (m == MM-1) {
        pc = PP-1;          // jax concatenates the exact endpoint
    } else {
        // out[m] = stop * (m/div), correctly-rounded fp32 regardless of fast-math
        float t = __fdiv_rn((float)m, (float)(MM-1));
        float v = __fmul_rn((float)(PP-1), t);
        pc = (int)v;        // floor for v >= 0
        if (pc > PP-1) pc = PP-1;
    }
    const float* s = xyz + ((size_t)(b*PP + pc))*3;
    out[(size_t)i*3 + 0] = s[0];
    out[(size_t)i*3 + 1] = s[1];
    out[(size_t)i*3 + 2] = s[2];
}

// ---------------- KNN: 2 centers per block, 256 threads ----------------
__global__ void __launch_bounds__(256) k_knn(const float* __restrict__ xyz,
                                             const float* __restrict__ centers,
                                             int* __restrict__ idxout) {
    extern __shared__ float dist[];   // [2][PP] = 64 KB
    __shared__ float red_v[8];
    __shared__ int   red_p[8];
    __shared__ int   swin_p;

    int tid  = threadIdx.x;
    int lane = tid & 31, wid = tid >> 5;
    int blk  = blockIdx.x;
    int b    = blk / (MM/2);
    int m0   = (blk % (MM/2)) * 2;

    float cx[2], cy[2], cz[2], cc2[2];
#pragma unroll
    for (int j = 0; j < 2; j++) {
        const float* cp = centers + ((size_t)(b*MM + m0 + j))*3;
        cx[j] = cp[0]; cy[j] = cp[1]; cz[j] = cp[2];
        cc2[j] = cx[j]*cx[j] + cy[j]*cy[j] + cz[j]*cz[j];
    }

    float myv[2] = {FLT_MAX, FLT_MAX};
    int   myp[2] = {0x7fffffff, 0x7fffffff};
    const float* xb = xyz + (size_t)b*PP*3;

    for (int i = 0; i < PP/256; i++) {
        int p = tid + i*256;
        float x = xb[p*3+0], y = xb[p*3+1], z = xb[p*3+2];
        float x2 = x*x + y*y + z*z;
#pragma unroll
        for (int j = 0; j < 2; j++) {
            float d = (cc2[j] + x2) - 2.0f*(cx[j]*x + cy[j]*y + cz[j]*z);
            dist[j*PP + p] = d;
            if (d < myv[j] || (d == myv[j] && p < myp[j])) { myv[j] = d; myp[j] = p; }
        }
    }
    __syncthreads();

    for (int j = 0; j < 2; j++) {
        float mv = myv[j]; int mp = myp[j];
        for (int it = 0; it < KK; it++) {
            float rv = mv; int rp = mp;
#pragma unroll
            for (int off = 16; off; off >>= 1) {
                float ov = __shfl_down_sync(0xffffffffu, rv, off);
                int   op = __shfl_down_sync(0xffffffffu, rp, off);
                if (ov < rv || (ov == rv && op < rp)) { rv = ov; rp = op; }
            }
            if (lane == 0) { red_v[wid] = rv; red_p[wid] = rp; }
            __syncthreads();
            if (tid == 0) {
                float bv = red_v[0]; int bp = red_p[0];
#pragma unroll
                for (int w = 1; w < 8; w++) {
                    float ov = red_v[w]; int op = red_p[w];
                    if (ov < bv || (ov == bv && op < bp)) { bv = ov; bp = op; }
                }
                swin_p = bp;
                idxout[((size_t)(b*MM + m0 + j))*KK + it] = bp;
            }
            __syncthreads();
            int wp = swin_p;
            int owner = wp & 255;
            if ((tid >> 5) == (owner >> 5)) {   // owner's warp rescans cooperatively
                if (tid == owner) dist[j*PP + wp] = FLT_MAX;
                __syncwarp();
                int p2 = owner + 256*lane;
                float dv = dist[j*PP + p2];
                int   pv = p2;
#pragma unroll
                for (int off = 16; off; off >>= 1) {
                    float ov = __shfl_xor_sync(0xffffffffu, dv, off);
                    int   op = __shfl_xor_sync(0xffffffffu, pv, off);
                    if (ov < dv || (ov == dv && op < pv)) { dv = ov; pv = op; }
                }
                if (tid == owner) { mv = dv; mp = pv; }
            }
            __syncthreads();
        }
    }
}

// ---------------- GEMM1: cat(67) -> h0(128), gather fused, stats accumulated ----------------
#define G1 4
__global__ void __launch_bounds__(128) k_gemm1(const float* __restrict__ xyz,
                                               const float* __restrict__ centers,
                                               const float* __restrict__ W1,
                                               const float* __restrict__ b1) {
    __shared__ float W1s[H1*CIN];       // 34304 B
    __shared__ float cat_s[CIN*KK];     // 8576 B
    __shared__ int   s_idx[KK];

    int tid = threadIdx.x;
    for (int i = tid; i < H1*CIN; i += 128) W1s[i] = W1[i];
    float bias = b1[tid];
    int b  = blockIdx.x / (MM/G1);
    int m0 = (blockIdx.x % (MM/G1)) * G1;
    float ssum = 0.f, ssq = 0.f;

    for (int g = 0; g < G1; g++) {
        int m = m0 + g;
        __syncthreads();
        if (tid < KK) s_idx[tid] = g_idx[((size_t)(b*MM + m))*KK + tid];
        __syncthreads();
        {
            int k = tid & 31, ch = tid >> 5;   // 4 chunks of 16 channels
            int p = s_idx[k];
            const float4* src = (const float4*)(g_featsT + ((size_t)(b*PP + p))*CC + ch*16);
#pragma unroll
            for (int q = 0; q < 4; q++) {
                float4 v = src[q];
                int c0 = 3 + ch*16 + q*4;
                cat_s[(c0+0)*KK + k] = v.x;
                cat_s[(c0+1)*KK + k] = v.y;
                cat_s[(c0+2)*KK + k] = v.z;
                cat_s[(c0+3)*KK + k] = v.w;
            }
            if (ch == 0) {
                const float* xp = xyz + ((size_t)(b*PP + p))*3;
                const float* cp = centers + ((size_t)(b*MM + m))*3;
                cat_s[0*KK + k] = xp[0] - cp[0];
                cat_s[1*KK + k] = xp[1] - cp[1];
                cat_s[2*KK + k] = xp[2] - cp[2];
            }
        }
        __syncthreads();

        float acc[KK];
#pragma unroll
        for (int k = 0; k < KK; k++) acc[k] = bias;
        const float* wrow = &W1s[tid*CIN];
#pragma unroll 4
        for (int c = 0; c < CIN; c++) {
            float w = wrow[c];
            const float4* row = (const float4*)&cat_s[c*KK];
#pragma unroll
            for (int q = 0; q < 8; q++) {
                float4 v = row[q];
                acc[q*4+0] += w*v.x; acc[q*4+1] += w*v.y;
                acc[q*4+2] += w*v.z; acc[q*4+3] += w*v.w;
            }
        }
        float* dst = g_h0 + ((size_t)(b*MM + m))*KK*H1;
#pragma unroll
        for (int k = 0; k < KK; k++) {
            float v = acc[k];
            dst[k*H1 + tid] = v;
            ssum += v; ssq += v*v;
        }
    }
    atomicAdd(&g_stats1[tid], ssum);
    atomicAdd(&g_stats1[H1 + tid], ssq);
}

// ---------------- BN affine finalize ----------------
__global__ void k_aff(const float* __restrict__ gg, const float* __restrict__ be,
                      const float* __restrict__ stats, float* __restrict__ aff) {
    int o = threadIdx.x;
    float inv = 1.0f / (float)NPIX;
    float mean = stats[o] * inv;
    float var  = stats[H1 + o] * inv - mean*mean;
    float a = gg[o] * rsqrtf(var + BN_EPS);
    aff[o] = a;
    aff[H1 + o] = be[o] - a*mean;
}

// ---------------- GEMM2: relu(bn(h0))(128) -> f0(128), stats accumulated ----------------
#define G2 4
__global__ void __launch_bounds__(128) k_gemm2(const float* __restrict__ W2,
                                               const float* __restrict__ b2) {
    extern __shared__ float sm[];
    float* W2s = sm;                 // 128*129
    float* h_s = sm + H1*129;        // 128*36

    int tid = threadIdx.x;
    for (int i = tid; i < H1*H1; i += 128) {
        int r = i / H1, c = i % H1;
        W2s[r*129 + c] = W2[i];
    }
    float a1 = g_aff1[tid], c1 = g_aff1[H1 + tid];
    float bias = b2[tid];
    int b  = blockIdx.x / (MM/G2);
    int m0 = (blockIdx.x % (MM/G2)) * G2;
    float ssum = 0.f, ssq = 0.f;

    for (int g = 0; g < G2; g++) {
        int m = m0 + g;
        size_t base = ((size_t)(b*MM + m))*KK*H1;
        __syncthreads();
#pragma unroll
        for (int i = 0; i < KK; i++) {
            float v = g_h0[base + i*H1 + tid];
            h_s[tid*36 + i] = fmaxf(a1*v + c1, 0.f);
        }
        __syncthreads();

        float acc[KK];
#pragma unroll
        for (int k = 0; k < KK; k++) acc[k] = bias;
        const float* wrow = &W2s[tid*129];
#pragma unroll 4
        for (int c = 0; c < H1; c++) {
            float w = wrow[c];
            const float4* row = (const float4*)&h_s[c*36];
#pragma unroll
            for (int q = 0; q < 8; q++) {
                float4 v = row[q];
                acc[q*4+0] += w*v.x; acc[q*4+1] += w*v.y;
                acc[q*4+2] += w*v.z; acc[q*4+3] += w*v.w;
            }
        }
        float* dst = g_f0 + base;
#pragma unroll
        for (int k = 0; k < KK; k++) {
            float v = acc[k];
            dst[k*H1 + tid] = v;
            ssum += v; ssq += v*v;
        }
    }
    atomicAdd(&g_stats2[tid], ssum);
    atomicAdd(&g_stats2[H1 + tid], ssq);
}

// ---------------- final: bn+relu, attention weights, softmax, aggregate ----------------
#define G3 8
__global__ void __launch_bounds__(128) k_final(const float* __restrict__ Wq1,
                                               const float* __restrict__ bq1,
                                               const float* __restrict__ Wq2,
                                               const float* __restrict__ bq2,
                                               float* __restrict__ out) {
    extern __shared__ float sm[];
    float* Wq1s = sm;                      // 64*129 = 8256
    float* fl_s = Wq1s + Q1*129;           // 128*36 = 4608
    float* q_s  = fl_s + H1*36;            // 64*36  = 2304
    float* Wq2s = q_s + Q1*36;             // 64
    float* w_s  = Wq2s + Q1;               // 32

    int tid = threadIdx.x;
    for (int i = tid; i < Q1*H1; i += 128) {
        int r = i / H1, c = i % H1;
        Wq1s[r*129 + c] = Wq1[i];
    }
    if (tid < Q1) Wq2s[tid] = Wq2[tid];
    float a2 = g_aff2[tid], c2v = g_aff2[H1 + tid];
    float bq2v = bq2[0];
    int b  = blockIdx.x / (MM/G3);
    int m0 = (blockIdx.x % (MM/G3)) * G3;

    for (int g = 0; g < G3; g++) {
        int m = m0 + g;
        size_t base = ((size_t)(b*MM + m))*KK*H1;
        __syncthreads();
#pragma unroll
        for (int i = 0; i < KK; i++) {
            float v = g_f0[base + i*H1 + tid];
            fl_s[tid*36 + i] = fmaxf(a2*v + c2v, 0.f);
        }
        __syncthreads();
        {   // q = relu(Wq1 @ feat_local + bq1): thread t -> (j = t&63, k-half = t>>6)
            int j = tid & 63, kh = tid >> 6;
            float qa[16];
            float bb = bq1[j];
#pragma unroll
            for (int t = 0; t < 16; t++) qa[t] = bb;
            const float* wrow = &Wq1s[j*129];
#pragma unroll 4
            for (int o = 0; o < H1; o++) {
                float w = wrow[o];
                const float4* row = (const float4*)&fl_s[o*36 + kh*16];
#pragma unroll
                for (int q = 0; q < 4; q++) {
                    float4 v = row[q];
                    qa[q*4+0] += w*v.x; qa[q*4+1] += w*v.y;
                    qa[q*4+2] += w*v.z; qa[q*4+3] += w*v.w;
                }
            }
#pragma unroll
            for (int t = 0; t < 16; t++) q_s[j*36 + kh*16 + t] = fmaxf(qa[t], 0.f);
        }
        __syncthreads();
        if (tid < KK) {   // warp 0: logits + softmax over K
            float acc = bq2v;
#pragma unroll 4
            for (int j = 0; j < Q1; j++) acc += Wq2s[j]*q_s[j*36 + tid];
            float mx = acc;
#pragma unroll
            for (int off = 16; off; off >>= 1)
                mx = fmaxf(mx, __shfl_xor_sync(0xffffffffu, mx, off));
            float e = expf(acc - mx);
            float s = e;
#pragma unroll
            for (int off = 16; off; off >>= 1)
                s += __shfl_xor_sync(0xffffffffu, s, off);
            w_s[tid] = e / s;
        }
        __syncthreads();
        {
            float acc = 0.f;
            const float4* row = (const float4*)&fl_s[tid*36];
#pragma unroll
            for (int q = 0; q < 8; q++) {
                float4 v  = row[q];
                float4 w4 = *(const float4*)&w_s[q*4];
                acc += v.x*w4.x + v.y*w4.y + v.z*w4.z + v.w*w4.w;
            }
            out[(size_t)BB*MM*3 + ((size_t)b*H1 + tid)*MM + m] = acc;
        }
    }
}

// ---------------- launch ----------------
extern "C" void kernel_launch(void* const* d_in, const int* in_sizes, int n_in,
                              void* d_out, int out_size) {
    const float* xyz  = (const float*)d_in[0];
    const float* feats= (const float*)d_in[1];
    const float* W1   = (const float*)d_in[2];
    const float* b1   = (const float*)d_in[3];
    const float* g1   = (const float*)d_in[4];
    const float* be1  = (const float*)d_in[5];
    const float* W2   = (const float*)d_in[6];
    const float* b2   = (const float*)d_in[7];
    const float* g2   = (const float*)d_in[8];
    const float* be2  = (const float*)d_in[9];
    const float* Wq1  = (const float*)d_in[10];
    const float* bq1  = (const float*)d_in[11];
    const float* Wq2  = (const float*)d_in[12];
    const float* bq2  = (const float*)d_in[13];
    float* out = (float*)d_out;

    void *s1, *s2, *idxp, *aff1p, *aff2p;
    cudaGetSymbolAddress(&s1, g_stats1);
    cudaGetSymbolAddress(&s2, g_stats2);
    cudaGetSymbolAddress(&idxp, g_idx);
    cudaGetSymbolAddress(&aff1p, g_aff1);
    cudaGetSymbolAddress(&aff2p, g_aff2);

    cudaFuncSetAttribute(k_knn,   cudaFuncAttributeMaxDynamicSharedMemorySize, 2*PP*4);
    cudaFuncSetAttribute(k_gemm2, cudaFuncAttributeMaxDynamicSharedMemorySize, (H1*129 + H1*36)*4);
    cudaFuncSetAttribute(k_final, cudaFuncAttributeMaxDynamicSharedMemorySize, (Q1*129 + H1*36 + Q1*36 + Q1 + KK)*4);

    cudaMemsetAsync(s1, 0, 2*H1*sizeof(float));
    cudaMemsetAsync(s2, 0, 2*H1*sizeof(float));

    k_pre<<<(BB*PP + 255)/256, 256>>>(feats);
    k_centers<<<(BB*MM + 255)/256, 256>>>(xyz, out);
    k_knn<<<BB*MM/2, 256, 2*PP*4>>>(xyz, out, (int*)idxp);
    k_gemm1<<<BB*MM/G1, 128>>>(xyz, out, W1, b1);
    k_aff<<<1, H1>>>(g1, be1, (const float*)s1, (float*)aff1p);
    k_gemm2<<<BB*MM/G2, 128, (H1*129 + H1*36)*4>>>(W2, b2);
    k_aff<<<1, H1>>>(g2, be2, (const float*)s2, (float*)aff2p);
    k_final<<<BB*MM/G3, 128, (Q1*129 + H1*36 + Q1*36 + Q1 + KK)*4>>>(Wq1, bq1, Wq2, bq2, out);
}

// round 5
// speedup vs baseline: 1.2913x; 1.2913x over previous
#include <cuda_runtime.h>
#include <math.h>
#include <float.h>

#define BB 4
#define PP 8192
#define CC 64
#define MM 2048
#define KK 32
#define CIN 67
#define H1 128
#define Q1 64
#define NPIX (BB*MM*KK)
#define BN_EPS 1e-5f
#define FULLMASK 0xffffffffu

#define G1N 4   // tiles per group, gemm1 (4 groups/block of 256)
#define G2N 4   // tiles per group, gemm2 (2 groups/block of 128)
#define G3N 4   // tiles per warp, final (4 warps/block of 128)

// ---------------- scratch (device globals; no allocation allowed) ----------------
__device__ float g_featsT[(size_t)BB*PP*CC];        // (B,P,C) transposed feats
__device__ int   g_idx[(size_t)BB*MM*KK];           // KNN indices
__device__ float g_h0[(size_t)BB*MM*H1*KK];         // conv1 pre-BN, layout [m][o][k]
__device__ float g_f0[(size_t)BB*MM*H1*KK];         // conv2 pre-BN, layout [m][o][k]
__device__ float g_stats1[2*H1];
__device__ float g_stats2[2*H1];
__device__ float g_aff1[2*H1];
__device__ float g_aff2[2*H1];

// ---------------- feats transpose (B,C,P) -> (B,P,C) ----------------
__global__ void k_pre(const float* __restrict__ feats) {
    int gp = blockIdx.x * blockDim.x + threadIdx.x;
    if (gp >= BB*PP) return;
    int b = gp / PP, p = gp % PP;
    const float* src = feats + (size_t)b*CC*PP + p;
    float4* dst = (float4*)(g_featsT + (size_t)gp*CC);
#pragma unroll
    for (int c0 = 0; c0 < CC; c0 += 4) {
        float4 v;
        v.x = src[(size_t)(c0+0)*PP];
        v.y = src[(size_t)(c0+1)*PP];
        v.z = src[(size_t)(c0+2)*PP];
        v.w = src[(size_t)(c0+3)*PP];
        dst[c0 >> 2] = v;
    }
}

// ---------------- centers (exact jax linspace semantics) ----------------
__global__ void k_centers(const float* __restrict__ xyz, float* __restrict__ out) {
    int i = blockIdx.x * blockDim.x + threadIdx.x;
    if (i >= BB*MM) return;
    int b = i / MM, m = i % MM;
    int pc;
    if (m == MM-1) {
        pc = PP-1;
    } else {
        float t = __fdiv_rn((float)m, (float)(MM-1));
        float v = __fmul_rn((float)(PP-1), t);
        pc = (int)v;
        if (pc > PP-1) pc = PP-1;
    }
    const float* s = xyz + ((size_t)(b*PP + pc))*3;
    out[(size_t)i*3 + 0] = s[0];
    out[(size_t)i*3 + 1] = s[1];
    out[(size_t)i*3 + 2] = s[2];
}

// ---------------- KNN: one warp per center, sorted top-32 insertion list ----------------
__global__ void __launch_bounds__(256) k_knn(const float* __restrict__ xyz,
                                             const float* __restrict__ centers,
                                             int* __restrict__ idxout) {
    int gw   = blockIdx.x * 8 + (threadIdx.x >> 5);   // global warp = center id
    int lane = threadIdx.x & 31;
    int b    = gw >> 11;                               // MM = 2048
    const float* cp = centers + (size_t)gw*3;
    float cx = cp[0], cy = cp[1], cz = cp[2];
    float cc2 = cx*cx + cy*cy + cz*cz;
    const float* xb = xyz + (size_t)b*PP*3;

    // sorted ascending list across lanes: lane r holds r-th smallest (d, idx)
    float ld = FLT_MAX; int li = 0x7fffffff;
    float kth = FLT_MAX;                               // broadcast of lane 31's d

    for (int base = 0; base < PP; base += 32) {
        int p = base + lane;
        float x = xb[3*p], y = xb[3*p+1], z = xb[3*p+2];
        float x2 = x*x + y*y + z*z;
        float d = (cc2 + x2) - 2.0f*(cx*x + cy*y + cz*z);
        unsigned mask = __ballot_sync(FULLMASK, d < kth);
        while (mask) {
            int j = __ffs(mask) - 1; mask &= mask - 1;
            float dj = __shfl_sync(FULLMASK, d, j);
            if (dj < kth) {                            // uniform branch (kth tightened)
                int pj = base + j;
                unsigned lt = __ballot_sync(FULLMASK, (ld < dj) || (ld == dj && li < pj));
                int pos = __popc(lt);
                float pd = __shfl_up_sync(FULLMASK, ld, 1);
                int   pi = __shfl_up_sync(FULLMASK, li, 1);
                if (lane == pos)      { ld = dj; li = pj; }
                else if (lane > pos)  { ld = pd; li = pi; }
                kth = __shfl_sync(FULLMASK, ld, 31);
            }
        }
    }
    idxout[(size_t)gw*KK + lane] = li;
}

// ---------------- GEMM1: cat(67)->h0(128), register-tiled 8x8, gather fused ----------------
// block 256 = 4 groups x 2 warps; group handles one m-tile at a time.
// warp layout: lane = kg*8 + og; warp w covers outs w*64 + og*8 + [0,8); ks kg*8 + [0,8)
__global__ void __launch_bounds__(256, 2) k_gemm1(const float* __restrict__ xyz,
                                                  const float* __restrict__ centers,
                                                  const float* __restrict__ W1,
                                                  const float* __restrict__ b1) {
    extern __shared__ float sm[];
    float* sw = sm;                               // CIN*128 floats (f4-tiled transposed W1)
    int tid  = threadIdx.x;
    int grp  = tid >> 6;
    int t2   = tid & 63;
    int w    = (tid >> 5) & 1;
    int lane = tid & 31;
    int og = lane & 7, kg = lane >> 3;
    float* cat = sm + CIN*128 + grp*(CIN*KK);     // per-group [c][k], stride 32

    // load W1 (global [o][c]) into tiled layout: f4idx = c*32 + w*16 + q*8 + og
    for (int i = tid; i < H1*CIN; i += 256) {
        int o = i / CIN, c = i - o*CIN;
        int ww = o >> 6, g8 = (o >> 3) & 7, q = (o >> 2) & 1, r = o & 3;
        sw[(c*32 + ww*16 + q*8 + g8)*4 + r] = W1[i];
    }
    float bj[8];
#pragma unroll
    for (int j = 0; j < 8; j++) bj[j] = b1[w*64 + og*8 + j];

    const int blocks_per_b = MM/(4*G1N);          // 128
    int b      = blockIdx.x / blocks_per_b;
    int m_base = (blockIdx.x % blocks_per_b) * (4*G1N);

    float ts[8], tq[8];
#pragma unroll
    for (int j = 0; j < 8; j++) { ts[j] = 0.f; tq[j] = 0.f; }

    const float4* wq = (const float4*)sw;
    const float4* dq = (const float4*)cat;

    for (int g = 0; g < G1N; g++) {
        int m = m_base + grp*G1N + g;
        __syncthreads();
        {   // gather: 64 threads of the group fill cat[67][32]
            int k = t2 & 31, half = t2 >> 5;
            int p = g_idx[((size_t)(b*MM + m))*KK + k];
            const float4* src = (const float4*)(g_featsT + ((size_t)(b*PP + p))*CC) + half*8;
#pragma unroll
            for (int q = 0; q < 8; q++) {
                float4 v = src[q];
                int c0 = 3 + half*32 + q*4;
                cat[(c0+0)*KK + k] = v.x;
                cat[(c0+1)*KK + k] = v.y;
                cat[(c0+2)*KK + k] = v.z;
                cat[(c0+3)*KK + k] = v.w;
            }
            if (half == 0) {
                const float* xp = xyz + ((size_t)(b*PP + p))*3;
                const float* cpt = centers + ((size_t)(b*MM + m))*3;
                cat[0*KK + k] = xp[0] - cpt[0];
                cat[1*KK + k] = xp[1] - cpt[1];
                cat[2*KK + k] = xp[2] - cpt[2];
            }
        }
        __syncthreads();

        float acc[8][8];
#pragma unroll
        for (int j = 0; j < 8; j++)
#pragma unroll
            for (int t = 0; t < 8; t++) acc[j][t] = bj[j];

#pragma unroll 4
        for (int c = 0; c < CIN; c++) {
            float4 wa = wq[c*32 + w*16 + og];
            float4 wb = wq[c*32 + w*16 + 8 + og];
            float4 da = dq[c*8 + kg*2];
            float4 db = dq[c*8 + kg*2 + 1];
            float wv[8] = {wa.x, wa.y, wa.z, wa.w, wb.x, wb.y, wb.z, wb.w};
            float dv[8] = {da.x, da.y, da.z, da.w, db.x, db.y, db.z, db.w};
#pragma unroll
            for (int j = 0; j < 8; j++)
#pragma unroll
                for (int t = 0; t < 8; t++)
                    acc[j][t] = fmaf(wv[j], dv[t], acc[j][t]);
        }

        float* dst = g_h0 + ((size_t)(b*MM + m))*(H1*KK);
#pragma unroll
        for (int j = 0; j < 8; j++) {
            int o = w*64 + og*8 + j;
            *(float4*)&dst[o*KK + kg*8]     = make_float4(acc[j][0], acc[j][1], acc[j][2], acc[j][3]);
            *(float4*)&dst[o*KK + kg*8 + 4] = make_float4(acc[j][4], acc[j][5], acc[j][6], acc[j][7]);
#pragma unroll
            for (int t = 0; t < 8; t++) { float v = acc[j][t]; ts[j] += v; tq[j] += v*v; }
        }
    }
    // reduce stats over kg (lanes with same og), then atomics from lanes 0-7
#pragma unroll
    for (int j = 0; j < 8; j++) {
        ts[j] += __shfl_down_sync(FULLMASK, ts[j], 16);
        ts[j] += __shfl_down_sync(FULLMASK, ts[j], 8);
        tq[j] += __shfl_down_sync(FULLMASK, tq[j], 16);
        tq[j] += __shfl_down_sync(FULLMASK, tq[j], 8);
    }
    if (lane < 8) {
#pragma unroll
        for (int j = 0; j < 8; j++) {
            int o = w*64 + lane*8 + j;
            atomicAdd(&g_stats1[o], ts[j]);
            atomicAdd(&g_stats1[H1 + o], tq[j]);
        }
    }
}

// ---------------- BN affine finalize ----------------
__global__ void k_aff(const float* __restrict__ gg, const float* __restrict__ be,
                      const float* __restrict__ stats, float* __restrict__ aff) {
    int o = threadIdx.x;
    float inv = 1.0f / (float)NPIX;
    float mean = stats[o] * inv;
    float var  = stats[H1 + o] * inv - mean*mean;
    float a = gg[o] * rsqrtf(var + BN_EPS);
    aff[o] = a;
    aff[H1 + o] = be[o] - a*mean;
}

// ---------------- GEMM2: relu(bn(h0))(128)->f0(128), register-tiled ----------------
// block 128 = 2 groups x 2 warps
__global__ void __launch_bounds__(128, 2) k_gemm2(const float* __restrict__ W2,
                                                  const float* __restrict__ b2) {
    extern __shared__ float sm[];
    float* sw    = sm;                    // H1*H1 floats
    float* aff1s = sm + H1*H1;            // 2*H1
    int tid  = threadIdx.x;
    int grp  = tid >> 6;
    int t2   = tid & 63;
    int w    = (tid >> 5) & 1;
    int lane = tid & 31;
    int og = lane & 7, kg = lane >> 3;
    float* hs = sm + H1*H1 + 2*H1 + grp*(H1*KK);   // [c][k], stride 32

    for (int i = tid; i < H1*H1; i += 128) {
        int o = i >> 7, c = i & 127;
        int ww = o >> 6, g8 = (o >> 3) & 7, q = (o >> 2) & 1, r = o & 3;
        sw[(c*32 + ww*16 + q*8 + g8)*4 + r] = W2[i];
    }
    for (int i = tid; i < 2*H1; i += 128) aff1s[i] = g_aff1[i];
    float bj[8];
#pragma unroll
    for (int j = 0; j < 8; j++) bj[j] = b2[w*64 + og*8 + j];

    const int blocks_per_b = MM/(2*G2N);          // 256
    int b      = blockIdx.x / blocks_per_b;
    int m_base = (blockIdx.x % blocks_per_b) * (2*G2N);

    float ts[8], tq[8];
#pragma unroll
    for (int j = 0; j < 8; j++) { ts[j] = 0.f; tq[j] = 0.f; }

    const float4* wq = (const float4*)sw;
    const float4* dq = (const float4*)hs;

    for (int g = 0; g < G2N; g++) {
        int m = m_base + grp*G2N + g;
        size_t base = ((size_t)(b*MM + m))*(H1*KK);
        __syncthreads();
        {   // load tile [c][k] contiguous, apply bn1+relu
            const float4* src = (const float4*)(g_h0 + base);
            float4* dstv = (float4*)hs;
            for (int i = t2; i < H1*KK/4; i += 64) {
                float4 v = src[i];
                int c = i >> 3;
                float a = aff1s[c], cc = aff1s[H1 + c];
                v.x = fmaxf(fmaf(a, v.x, cc), 0.f);
                v.y = fmaxf(fmaf(a, v.y, cc), 0.f);
                v.z = fmaxf(fmaf(a, v.z, cc), 0.f);
                v.w = fmaxf(fmaf(a, v.w, cc), 0.f);
                dstv[i] = v;
            }
        }
        __syncthreads();

        float acc[8][8];
#pragma unroll
        for (int j = 0; j < 8; j++)
#pragma unroll
            for (int t = 0; t < 8; t++) acc[j][t] = bj[j];

#pragma unroll 4
        for (int c = 0; c < H1; c++) {
            float4 wa = wq[c*32 + w*16 + og];
            float4 wb = wq[c*32 + w*16 + 8 + og];
            float4 da = dq[c*8 + kg*2];
            float4 db = dq[c*8 + kg*2 + 1];
            float wv[8] = {wa.x, wa.y, wa.z, wa.w, wb.x, wb.y, wb.z, wb.w};
            float dv[8] = {da.x, da.y, da.z, da.w, db.x, db.y, db.z, db.w};
#pragma unroll
            for (int j = 0; j < 8; j++)
#pragma unroll
                for (int t = 0; t < 8; t++)
                    acc[j][t] = fmaf(wv[j], dv[t], acc[j][t]);
        }

        float* dst = g_f0 + base;
#pragma unroll
        for (int j = 0; j < 8; j++) {
            int o = w*64 + og*8 + j;
            *(float4*)&dst[o*KK + kg*8]     = make_float4(acc[j][0], acc[j][1], acc[j][2], acc[j][3]);
            *(float4*)&dst[o*KK + kg*8 + 4] = make_float4(acc[j][4], acc[j][5], acc[j][6], acc[j][7]);
#pragma unroll
            for (int t = 0; t < 8; t++) { float v = acc[j][t]; ts[j] += v; tq[j] += v*v; }
        }
    }
#pragma unroll
    for (int j = 0; j < 8; j++) {
        ts[j] += __shfl_down_sync(FULLMASK, ts[j], 16);
        ts[j] += __shfl_down_sync(FULLMASK, ts[j], 8);
        tq[j] += __shfl_down_sync(FULLMASK, tq[j], 16);
        tq[j] += __shfl_down_sync(FULLMASK, tq[j], 8);
    }
    if (lane < 8) {
#pragma unroll
        for (int j = 0; j < 8; j++) {
            int o = w*64 + lane*8 + j;
            atomicAdd(&g_stats2[o], ts[j]);
            atomicAdd(&g_stats2[H1 + o], tq[j]);
        }
    }
}

// ---------------- final: bn2+relu, attention GEMM (64), softmax, aggregate ----------------
// block 128 = 4 warps, one warp per tile. fl stride = 36 floats (aligned, low-conflict).
__global__ void __launch_bounds__(128, 2) k_final(const float* __restrict__ Wq1,
                                                  const float* __restrict__ bq1,
                                                  const float* __restrict__ Wq2,
                                                  const float* __restrict__ bq2,
                                                  float* __restrict__ out) {
    extern __shared__ float sm[];
    float* swq   = sm;                       // Q1*H1 floats (tiled transposed Wq1)
    float* aff2s = sm + Q1*H1;               // 2*H1
    float* bq1s  = aff2s + 2*H1;             // Q1
    float* wq2s  = bq1s + Q1;                // Q1
    float* flall = wq2s + Q1 + 32;           // 4 * (H1*36), padded to keep 16B align
    float* wsall = flall + 4*(H1*36);        // 4 * 32

    int tid  = threadIdx.x;
    int wid  = tid >> 5;
    int lane = tid & 31;
    int og = lane & 7, kg = lane >> 3;

    for (int i = tid; i < Q1*H1; i += 128) {
        int j = i >> 7, c = i & 127;
        int g8 = (j >> 3) & 7, q = (j >> 2) & 1, r = j & 3;
        swq[(c*16 + q*8 + g8)*4 + r] = Wq1[i];
    }
    for (int i = tid; i < 2*H1; i += 128) aff2s[i] = g_aff2[i];
    if (tid < Q1) { bq1s[tid] = bq1[tid]; wq2s[tid] = Wq2[tid]; }
    __syncthreads();

    float* fl  = flall + wid*(H1*36);
    float* wsw = wsall + wid*32;

    float bjq[8], wq2v[8];
#pragma unroll
    for (int j = 0; j < 8; j++) { bjq[j] = bq1s[og*8 + j]; wq2v[j] = wq2s[og*8 + j]; }

    const int blocks_per_b = MM/(4*G3N);     // 128
    int b      = blockIdx.x / blocks_per_b;
    int m_base = (blockIdx.x % blocks_per_b) * (4*G3N);
    size_t obase = (size_t)BB*MM*3 + (size_t)b*H1*MM;

    const float4* wq = (const float4*)swq;
    const float4* dfl = (const float4*)fl;

    for (int g = 0; g < G3N; g++) {
        int m = m_base + wid*G3N + g;
        size_t base = ((size_t)(b*MM + m))*(H1*KK);

        {   // load tile, bn2+relu, into fl [c][k] stride 36
            const float4* src = (const float4*)(g_f0 + base);
            for (int i = lane; i < H1*KK/4; i += 32) {
                float4 v = src[i];
                int c = i >> 3, jj = i & 7;
                float a = aff2s[c], cc = aff2s[H1 + c];
                v.x = fmaxf(fmaf(a, v.x, cc), 0.f);
                v.y = fmaxf(fmaf(a, v.y, cc), 0.f);
                v.z = fmaxf(fmaf(a, v.z, cc), 0.f);
                v.w = fmaxf(fmaf(a, v.w, cc), 0.f);
                *(float4*)&fl[c*36 + jj*4] = v;
            }
        }
        __syncwarp();

        // q = Wq1 @ fl  (one warp covers 64 x 32)
        float acc[8][8];
#pragma unroll
        for (int j = 0; j < 8; j++)
#pragma unroll
            for (int t = 0; t < 8; t++) acc[j][t] = bjq[j];

#pragma unroll 4
        for (int c = 0; c < H1; c++) {
            float4 wa = wq[c*16 + og];
            float4 wb = wq[c*16 + 8 + og];
            float4 da = dfl[c*9 + kg*2];
            float4 db = dfl[c*9 + kg*2 + 1];
            float wv[8] = {wa.x, wa.y, wa.z, wa.w, wb.x, wb.y, wb.z, wb.w};
            float dv[8] = {da.x, da.y, da.z, da.w, db.x, db.y, db.z, db.w};
#pragma unroll
            for (int j = 0; j < 8; j++)
#pragma unroll
                for (int t = 0; t < 8; t++)
                    acc[j][t] = fmaf(wv[j], dv[t], acc[j][t]);
        }

        // logits partial over this lane's 8 j (softmax is shift-invariant: bq2 dropped)
        float lg[8];
#pragma unroll
        for (int t = 0; t < 8; t++) {
            float s = 0.f;
#pragma unroll
            for (int j = 0; j < 8; j++) s = fmaf(wq2v[j], fmaxf(acc[j][t], 0.f), s);
            lg[t] = s;
        }
        // reduce over og lanes (xor 1,2,4), then softmax across kg groups (xor 8,16)
#pragma unroll
        for (int t = 0; t < 8; t++) {
            lg[t] += __shfl_xor_sync(FULLMASK, lg[t], 1);
            lg[t] += __shfl_xor_sync(FULLMASK, lg[t], 2);
            lg[t] += __shfl_xor_sync(FULLMASK, lg[t], 4);
        }
        float mx = lg[0];
#pragma unroll
        for (int t = 1; t < 8; t++) mx = fmaxf(mx, lg[t]);
        mx = fmaxf(mx, __shfl_xor_sync(FULLMASK, mx, 8));
        mx = fmaxf(mx, __shfl_xor_sync(FULLMASK, mx, 16));
        float e[8], ssum = 0.f;
#pragma unroll
        for (int t = 0; t < 8; t++) { e[t] = expf(lg[t] - mx); ssum += e[t]; }
        ssum += __shfl_xor_sync(FULLMASK, ssum, 8);
        ssum += __shfl_xor_sync(FULLMASK, ssum, 16);
        float rs = 1.0f / ssum;
        if (og == 0) {
            *(float4*)&wsw[kg*8]     = make_float4(e[0]*rs, e[1]*rs, e[2]*rs, e[3]*rs);
            *(float4*)&wsw[kg*8 + 4] = make_float4(e[4]*rs, e[5]*rs, e[6]*rs, e[7]*rs);
        }
        __syncwarp();

        // aggregate: out[o] = sum_k fl[o][k] * w[k]
        float4 wsv[8];
#pragma unroll
        for (int q = 0; q < 8; q++) wsv[q] = ((const float4*)wsw)[q];
#pragma unroll
        for (int jo = 0; jo < 4; jo++) {
            int o = jo*32 + lane;
            const float4* fr = (const float4*)&fl[o*36];
            float a = 0.f;
#pragma unroll
            for (int q = 0; q < 8; q++) {
                float4 fv = fr[q];
                a = fmaf(fv.x, wsv[q].x, a);
                a = fmaf(fv.y, wsv[q].y, a);
                a = fmaf(fv.z, wsv[q].z, a);
                a = fmaf(fv.w, wsv[q].w, a);
            }
            out[obase + (size_t)o*MM + m] = a;
        }
        __syncwarp();
    }
}

// ---------------- launch ----------------
extern "C" void kernel_launch(void* const* d_in, const int* in_sizes, int n_in,
                              void* d_out, int out_size) {
    const float* xyz  = (const float*)d_in[0];
    const float* feats= (const float*)d_in[1];
    const float* W1   = (const float*)d_in[2];
    const float* b1   = (const float*)d_in[3];
    const float* g1   = (const float*)d_in[4];
    const float* be1  = (const float*)d_in[5];
    const float* W2   = (const float*)d_in[6];
    const float* b2   = (const float*)d_in[7];
    const float* g2   = (const float*)d_in[8];
    const float* be2  = (const float*)d_in[9];
    const float* Wq1  = (const float*)d_in[10];
    const float* bq1  = (const float*)d_in[11];
    const float* Wq2  = (const float*)d_in[12];
    const float* bq2  = (const float*)d_in[13];
    float* out = (float*)d_out;

    void *s1, *s2, *idxp, *aff1p, *aff2p;
    cudaGetSymbolAddress(&s1, g_stats1);
    cudaGetSymbolAddress(&s2, g_stats2);
    cudaGetSymbolAddress(&idxp, g_idx);
    cudaGetSymbolAddress(&aff1p, g_aff1);
    cudaGetSymbolAddress(&aff2p, g_aff2);

    const int smem1 = (CIN*128 + 4*CIN*KK)*4;                         // 68,608 B
    const int smem2 = (H1*H1 + 2*H1 + 2*H1*KK)*4;                     // 99,328 B
    const int smem3 = (Q1*H1 + 2*H1 + 2*Q1 + 32 + 4*H1*36 + 4*32)*4; // ~108.8 KB

    cudaFuncSetAttribute(k_gemm1, cudaFuncAttributeMaxDynamicSharedMemorySize, smem1);
    cudaFuncSetAttribute(k_gemm2, cudaFuncAttributeMaxDynamicSharedMemorySize, smem2);
    cudaFuncSetAttribute(k_final, cudaFuncAttributeMaxDynamicSharedMemorySize, smem3);

    cudaMemsetAsync(s1, 0, 2*H1*sizeof(float));
    cudaMemsetAsync(s2, 0, 2*H1*sizeof(float));

    k_pre<<<(BB*PP + 255)/256, 256>>>(feats);
    k_centers<<<(BB*MM + 255)/256, 256>>>(xyz, out);
    k_knn<<<BB*MM/8, 256>>>(xyz, out, (int*)idxp);
    k_gemm1<<<BB*MM/(4*G1N), 256, smem1>>>(xyz, out, W1, b1);
    k_aff<<<1, H1>>>(g1, be1, (const float*)s1, (float*)aff1p);
    k_gemm2<<<BB*MM/(2*G2N), 128, smem2>>>(W2, b2);
    k_aff<<<1, H1>>>(g2, be2, (const float*)s2, (float*)aff2p);
    k_final<<<BB*MM/(4*G3N), 128, smem3>>>(Wq1, bq1, Wq2, bq2, out);
}

// round 7
// speedup vs baseline: 2.7741x; 2.1483x over previous
#include <cuda_runtime.h>
#include <cuda_fp16.h>
#include <math.h>
#include <float.h>

#define BB 4
#define PP 8192
#define CC 64
#define MM 2048
#define KK 32
#define CIN 67
#define H1 128
#define Q1 64
#define NPIX (BB*MM*KK)
#define BN_EPS 1e-5f
#define FULLMASK 0xffffffffu

// ---------------- scratch ----------------
__device__ float g_featsT[(size_t)BB*PP*CC];        // (B,P,C)
__device__ int   g_idx[(size_t)BB*MM*KK];
__device__ float g_h0[(size_t)NPIX*H1];             // [pix][o] fp32
__device__ float g_f0[(size_t)NPIX*H1];             // [pix][o] fp32
__device__ float g_stats1[2*H1];
__device__ float g_stats2[2*H1];
__device__ float g_aff1[2*H1];
__device__ float g_aff2[2*H1];

// ---------------- warp MMA helper (m16n8k16, f16 in, f32 acc) ----------------
__device__ __forceinline__ void mma16816(float* c, const unsigned* a, const unsigned* b) {
    asm volatile(
        "mma.sync.aligned.m16n8k16.row.col.f32.f16.f16.f32 "
        "{%0,%1,%2,%3}, {%4,%5,%6,%7}, {%8,%9}, {%0,%1,%2,%3};"
        : "+f"(c[0]), "+f"(c[1]), "+f"(c[2]), "+f"(c[3])
        : "r"(a[0]), "r"(a[1]), "r"(a[2]), "r"(a[3]), "r"(b[0]), "r"(b[1]));
}

// ---------------- feats transpose ----------------
__global__ void k_pre(const float* __restrict__ feats) {
    int gp = blockIdx.x * blockDim.x + threadIdx.x;
    if (gp >= BB*PP) return;
    int b = gp / PP, p = gp % PP;
    const float* src = feats + (size_t)b*CC*PP + p;
    float4* dst = (float4*)(g_featsT + (size_t)gp*CC);
#pragma unroll
    for (int c0 = 0; c0 < CC; c0 += 4) {
        float4 v;
        v.x = src[(size_t)(c0+0)*PP];
        v.y = src[(size_t)(c0+1)*PP];
        v.z = src[(size_t)(c0+2)*PP];
        v.w = src[(size_t)(c0+3)*PP];
        dst[c0 >> 2] = v;
    }
}

// ---------------- centers (exact jax linspace) ----------------
__global__ void k_centers(const float* __restrict__ xyz, float* __restrict__ out) {
    int i = blockIdx.x * blockDim.x + threadIdx.x;
    if (i >= BB*MM) return;
    int b = i / MM, m = i % MM;
    int pc;
    if (m == MM-1) pc = PP-1;
    else {
        float t = __fdiv_rn((float)m, (float)(MM-1));
        float v = __fmul_rn((float)(PP-1), t);
        pc = (int)v;
        if (pc > PP-1) pc = PP-1;
    }
    const float* s = xyz + ((size_t)(b*PP + pc))*3;
    out[(size_t)i*3 + 0] = s[0];
    out[(size_t)i*3 + 1] = s[1];
    out[(size_t)i*3 + 2] = s[2];
}

// ---------------- KNN: one warp per center ----------------
__global__ void __launch_bounds__(256) k_knn(const float* __restrict__ xyz,
                                             const float* __restrict__ centers,
                                             int* __restrict__ idxout) {
    int gw   = blockIdx.x * 8 + (threadIdx.x >> 5);
    int lane = threadIdx.x & 31;
    int b    = gw >> 11;
    const float* cp = centers + (size_t)gw*3;
    float cx = cp[0], cy = cp[1], cz = cp[2];
    float cc2 = cx*cx + cy*cy + cz*cz;
    const float* xb = xyz + (size_t)b*PP*3;

    float ld = FLT_MAX; int li = 0x7fffffff;
    float kth = FLT_MAX;

    for (int base = 0; base < PP; base += 32) {
        int p = base + lane;
        float x = xb[3*p], y = xb[3*p+1], z = xb[3*p+2];
        float x2 = x*x + y*y + z*z;
        float d = (cc2 + x2) - 2.0f*(cx*x + cy*y + cz*z);
        unsigned mask = __ballot_sync(FULLMASK, d < kth);
        while (mask) {
            int j = __ffs(mask) - 1; mask &= mask - 1;
            float dj = __shfl_sync(FULLMASK, d, j);
            if (dj < kth) {
                int pj = base + j;
                unsigned lt = __ballot_sync(FULLMASK, (ld < dj) || (ld == dj && li < pj));
                int pos = __popc(lt);
                float pd = __shfl_up_sync(FULLMASK, ld, 1);
                int   pi = __shfl_up_sync(FULLMASK, li, 1);
                if (lane == pos)      { ld = dj; li = pj; }
                else if (lane > pos)  { ld = pd; li = pi; }
                kth = __shfl_sync(FULLMASK, ld, 31);
            }
        }
    }
    idxout[(size_t)gw*KK + lane] = li;
}

// ================= GEMM1: gather + [128pix x 80k] x [80k x 128o] per tile =================
__global__ void __launch_bounds__(256, 2) k_gemm1(const float* __restrict__ xyz,
                                                  const float* __restrict__ centers,
                                                  const float* __restrict__ W1,
                                                  const float* __restrict__ b1) {
    extern __shared__ __half sh[];
    __half* As = sh;                 // 128*88 halfs (44 words/row)
    __half* Bs = sh + 128*88;
    unsigned* Aw = (unsigned*)As;
    unsigned* Bw = (unsigned*)Bs;
    __half2* Ah2 = (__half2*)As;

    int tid = threadIdx.x, wid = tid >> 5, lane = tid & 31;
    int g = lane >> 2, t = lane & 3;
    int warp_pix = (wid >> 2) * 64, warp_n = (wid & 3) * 32;

    for (int i = tid; i < 128*44; i += 256) Bw[i] = 0u;
    __syncthreads();
    for (int i = tid; i < H1*CIN; i += 256) {
        int o = i / CIN, c = i - o*CIN;
        int col = (c < 3) ? (64 + c) : (c - 3);
        Bs[o*88 + col] = __float2half_rn(W1[i]);
    }
    float bias0[4], bias1[4];
#pragma unroll
    for (int ni = 0; ni < 4; ni++) {
        bias0[ni] = b1[warp_n + ni*8 + 2*t];
        bias1[ni] = b1[warp_n + ni*8 + 2*t + 1];
    }

    int b      = blockIdx.x / (MM/16);
    int m_base = (blockIdx.x % (MM/16)) * 16;
    int r = tid >> 1, h = tid & 1;

    float ss[4][2], sq[4][2];
#pragma unroll
    for (int ni = 0; ni < 4; ni++) { ss[ni][0]=ss[ni][1]=0.f; sq[ni][0]=sq[ni][1]=0.f; }

    for (int tile = 0; tile < 4; tile++) {
        int m0 = m_base + tile*4;
        size_t pixbase = ((size_t)(b*MM + m0))*KK;
        __syncthreads();
        {   // gather: 2 threads per pixel row (feats = 64 cols, h covers 32 each)
            int p = g_idx[pixbase + r];
            const float4* src = (const float4*)(g_featsT + ((size_t)(b*PP + p))*CC) + h*8;
            int wbase = r*44 + h*16;            // half2 units (row = 44 half2)
#pragma unroll
            for (int q = 0; q < 8; q++) {
                float4 v = src[q];
                Ah2[wbase + 2*q]     = __floats2half2_rn(v.x, v.y);
                Ah2[wbase + 2*q + 1] = __floats2half2_rn(v.z, v.w);
            }
            if (h == 0) {
                int m = m0 + (r >> 5);
                const float* xp = xyz + ((size_t)(b*PP + p))*3;
                const float* cpt = centers + ((size_t)(b*MM + m))*3;
                Ah2[r*44 + 32] = __floats2half2_rn(xp[0]-cpt[0], xp[1]-cpt[1]);
                Ah2[r*44 + 33] = __floats2half2_rn(xp[2]-cpt[2], 0.f);
#pragma unroll
                for (int q = 34; q < 44; q++) Ah2[r*44 + q] = __floats2half2_rn(0.f, 0.f);
            }
        }
        __syncthreads();

        float acc[4][4][4];
#pragma unroll
        for (int mi = 0; mi < 4; mi++)
#pragma unroll
            for (int ni = 0; ni < 4; ni++) {
                acc[mi][ni][0] = bias0[ni]; acc[mi][ni][1] = bias1[ni];
                acc[mi][ni][2] = bias0[ni]; acc[mi][ni][3] = bias1[ni];
            }
#pragma unroll
        for (int ks = 0; ks < 5; ks++) {
            int kw = ks*8;
            unsigned af[4][4], bf[4][2];
#pragma unroll
            for (int mi = 0; mi < 4; mi++) {
                int rr = warp_pix + mi*16 + g;
                af[mi][0] = Aw[rr*44 + t + kw];
                af[mi][1] = Aw[(rr+8)*44 + t + kw];
                af[mi][2] = Aw[rr*44 + t + 4 + kw];
                af[mi][3] = Aw[(rr+8)*44 + t + 4 + kw];
            }
#pragma unroll
            for (int ni = 0; ni < 4; ni++) {
                int nn = warp_n + ni*8 + g;
                bf[ni][0] = Bw[nn*44 + t + kw];
                bf[ni][1] = Bw[nn*44 + t + 4 + kw];
            }
#pragma unroll
            for (int mi = 0; mi < 4; mi++)
#pragma unroll
                for (int ni = 0; ni < 4; ni++)
                    mma16816(acc[mi][ni], af[mi], bf[ni]);
        }
#pragma unroll
        for (int mi = 0; mi < 4; mi++) {
            int row = warp_pix + mi*16 + g;
#pragma unroll
            for (int ni = 0; ni < 4; ni++) {
                int col = warp_n + ni*8 + 2*t;
                float* a = acc[mi][ni];
                *(float2*)&g_h0[(pixbase + row)*H1 + col]     = make_float2(a[0], a[1]);
                *(float2*)&g_h0[(pixbase + row + 8)*H1 + col] = make_float2(a[2], a[3]);
                ss[ni][0] += a[0] + a[2];  ss[ni][1] += a[1] + a[3];
                sq[ni][0] += a[0]*a[0] + a[2]*a[2];
                sq[ni][1] += a[1]*a[1] + a[3]*a[3];
            }
        }
    }
#pragma unroll
    for (int ni = 0; ni < 4; ni++)
#pragma unroll
        for (int j = 0; j < 2; j++) {
            float s = ss[ni][j], q = sq[ni][j];
            s += __shfl_xor_sync(FULLMASK, s, 4);  q += __shfl_xor_sync(FULLMASK, q, 4);
            s += __shfl_xor_sync(FULLMASK, s, 8);  q += __shfl_xor_sync(FULLMASK, q, 8);
            s += __shfl_xor_sync(FULLMASK, s, 16); q += __shfl_xor_sync(FULLMASK, q, 16);
            if (g == 0) {
                int o = warp_n + ni*8 + 2*t + j;
                atomicAdd(&g_stats1[o], s);
                atomicAdd(&g_stats1[H1 + o], q);
            }
        }
}

// ---------------- BN affine ----------------
__global__ void k_aff(const float* __restrict__ gg, const float* __restrict__ be,
                      const float* __restrict__ stats, float* __restrict__ aff) {
    int o = threadIdx.x;
    float inv = 1.0f / (float)NPIX;
    float mean = stats[o] * inv;
    float var  = stats[H1 + o] * inv - mean*mean;
    float a = gg[o] * rsqrtf(var + BN_EPS);
    aff[o] = a;
    aff[H1 + o] = be[o] - a*mean;
}

// ================= GEMM2: relu(bn1(h0)) [128 x 128] x W2^T =================
__global__ void __launch_bounds__(256, 2) k_gemm2(const float* __restrict__ W2,
                                                  const float* __restrict__ b2) {
    extern __shared__ __half sh[];
    __half* As = sh;                  // 128*136 halfs (68 words/row)
    __half* Bs = sh + 128*136;
    float* aff1s = (float*)(sh + 2*128*136);
    unsigned* Aw = (unsigned*)As;
    unsigned* Bw = (unsigned*)Bs;
    __half2* Ah2 = (__half2*)As;
    __half2* Bh2 = (__half2*)Bs;

    int tid = threadIdx.x, wid = tid >> 5, lane = tid & 31;
    int g = lane >> 2, t = lane & 3;
    int warp_pix = (wid >> 2) * 64, warp_n = (wid & 3) * 32;

    for (int i = tid; i < H1*64; i += 256) {
        int o = i >> 6, wp = i & 63;
        float2 v = ((const float2*)W2)[o*64 + wp];
        Bh2[o*68 + wp] = __floats2half2_rn(v.x, v.y);
    }
    for (int i = tid; i < 2*H1; i += 256) aff1s[i] = g_aff1[i];
    float bias0[4], bias1[4];
#pragma unroll
    for (int ni = 0; ni < 4; ni++) {
        bias0[ni] = b2[warp_n + ni*8 + 2*t];
        bias1[ni] = b2[warp_n + ni*8 + 2*t + 1];
    }

    int b      = blockIdx.x / (MM/16);
    int m_base = (blockIdx.x % (MM/16)) * 16;
    int r = tid >> 1, h = tid & 1;

    float ss[4][2], sq[4][2];
#pragma unroll
    for (int ni = 0; ni < 4; ni++) { ss[ni][0]=ss[ni][1]=0.f; sq[ni][0]=sq[ni][1]=0.f; }

    for (int tile = 0; tile < 4; tile++) {
        size_t pixbase = ((size_t)(b*MM + m_base + tile*4))*KK;
        __syncthreads();
        {   // load + bn1 + relu + cvt — FULL 128-col row: 16 float4 per thread
            const float4* src = (const float4*)(g_h0 + (pixbase + r)*H1) + h*16;
            int wbase = r*68 + h*32;            // half2 units (row = 68 half2)
#pragma unroll
            for (int q = 0; q < 16; q++) {
                float4 v = src[q];
                int c = h*64 + q*4;
                float4 a = *(const float4*)&aff1s[c];
                float4 cc = *(const float4*)&aff1s[H1 + c];
                v.x = fmaxf(fmaf(a.x, v.x, cc.x), 0.f);
                v.y = fmaxf(fmaf(a.y, v.y, cc.y), 0.f);
                v.z = fmaxf(fmaf(a.z, v.z, cc.z), 0.f);
                v.w = fmaxf(fmaf(a.w, v.w, cc.w), 0.f);
                Ah2[wbase + 2*q]     = __floats2half2_rn(v.x, v.y);
                Ah2[wbase + 2*q + 1] = __floats2half2_rn(v.z, v.w);
            }
        }
        __syncthreads();

        float acc[4][4][4];
#pragma unroll
        for (int mi = 0; mi < 4; mi++)
#pragma unroll
            for (int ni = 0; ni < 4; ni++) {
                acc[mi][ni][0] = bias0[ni]; acc[mi][ni][1] = bias1[ni];
                acc[mi][ni][2] = bias0[ni]; acc[mi][ni][3] = bias1[ni];
            }
#pragma unroll
        for (int ks = 0; ks < 8; ks++) {
            int kw = ks*8;
            unsigned af[4][4], bf[4][2];
#pragma unroll
            for (int mi = 0; mi < 4; mi++) {
                int rr = warp_pix + mi*16 + g;
                af[mi][0] = Aw[rr*68 + t + kw];
                af[mi][1] = Aw[(rr+8)*68 + t + kw];
                af[mi][2] = Aw[rr*68 + t + 4 + kw];
                af[mi][3] = Aw[(rr+8)*68 + t + 4 + kw];
            }
#pragma unroll
            for (int ni = 0; ni < 4; ni++) {
                int nn = warp_n + ni*8 + g;
                bf[ni][0] = Bw[nn*68 + t + kw];
                bf[ni][1] = Bw[nn*68 + t + 4 + kw];
            }
#pragma unroll
            for (int mi = 0; mi < 4; mi++)
#pragma unroll
                for (int ni = 0; ni < 4; ni++)
                    mma16816(acc[mi][ni], af[mi], bf[ni]);
        }
#pragma unroll
        for (int mi = 0; mi < 4; mi++) {
            int row = warp_pix + mi*16 + g;
#pragma unroll
            for (int ni = 0; ni < 4; ni++) {
                int col = warp_n + ni*8 + 2*t;
                float* a = acc[mi][ni];
                *(float2*)&g_f0[(pixbase + row)*H1 + col]     = make_float2(a[0], a[1]);
                *(float2*)&g_f0[(pixbase + row + 8)*H1 + col] = make_float2(a[2], a[3]);
                ss[ni][0] += a[0] + a[2];  ss[ni][1] += a[1] + a[3];
                sq[ni][0] += a[0]*a[0] + a[2]*a[2];
                sq[ni][1] += a[1]*a[1] + a[3]*a[3];
            }
        }
    }
#pragma unroll
    for (int ni = 0; ni < 4; ni++)
#pragma unroll
        for (int j = 0; j < 2; j++) {
            float s = ss[ni][j], q = sq[ni][j];
            s += __shfl_xor_sync(FULLMASK, s, 4);  q += __shfl_xor_sync(FULLMASK, q, 4);
            s += __shfl_xor_sync(FULLMASK, s, 8);  q += __shfl_xor_sync(FULLMASK, q, 8);
            s += __shfl_xor_sync(FULLMASK, s, 16); q += __shfl_xor_sync(FULLMASK, q, 16);
            if (g == 0) {
                int o = warp_n + ni*8 + 2*t + j;
                atomicAdd(&g_stats2[o], s);
                atomicAdd(&g_stats2[H1 + o], q);
            }
        }
}

// ================= final: bn2+relu, q-GEMM, softmax, fp32 aggregate ====
__global__ void __launch_bounds__(256, 2) k_final(const float* __restrict__ Wq1,
                                                  const float* __restrict__ bq1,
                                                  const float* __restrict__ Wq2,
                                                  const float* __restrict__ bq2,
                                                  float* __restrict__ out) {
    extern __shared__ __half sh[];
    __half* As = sh;                  // 128*136
    __half* Bs = sh + 128*136;        // 64*136
    float* aff2s = (float*)(sh + 128*136 + 64*136);
    float* bq1s  = aff2s + 2*H1;
    float* wq2s  = bq1s + Q1;
    float* slog0 = wq2s + Q1;
    float* slog1 = slog0 + 128;
    float* wk    = slog1 + 128;
    unsigned* Aw = (unsigned*)As;
    unsigned* Bw = (unsigned*)Bs;
    __half2* Ah2 = (__half2*)As;
    __half2* Bh2 = (__half2*)Bs;

    int tid = threadIdx.x, wid = tid >> 5, lane = tid & 31;
    int g = lane >> 2, t = lane & 3;
    int warp_pix = (wid & 3) * 32, warp_n = (wid >> 2) * 32;

    for (int i = tid; i < Q1*64; i += 256) {
        int n = i >> 6, wp = i & 63;
        float2 v = ((const float2*)Wq1)[n*64 + wp];
        Bh2[n*68 + wp] = __floats2half2_rn(v.x, v.y);
    }
    for (int i = tid; i < 2*H1; i += 256) aff2s[i] = g_aff2[i];
    if (tid < Q1) { bq1s[tid] = bq1[tid]; wq2s[tid] = Wq2[tid]; }

    float bias0[4], bias1[4], w20[4], w21[4];
    __syncthreads();
#pragma unroll
    for (int ni = 0; ni < 4; ni++) {
        bias0[ni] = bq1s[warp_n + ni*8 + 2*t];
        bias1[ni] = bq1s[warp_n + ni*8 + 2*t + 1];
        w20[ni]   = wq2s[warp_n + ni*8 + 2*t];
        w21[ni]   = wq2s[warp_n + ni*8 + 2*t + 1];
    }

    int b      = blockIdx.x / (MM/16);
    int m_base = (blockIdx.x % (MM/16)) * 16;
    int r = tid >> 1, h = tid & 1;
    size_t obase = (size_t)BB*MM*3 + (size_t)b*H1*MM;

    for (int tile = 0; tile < 4; tile++) {
        int m0 = m_base + tile*4;
        size_t pixbase = ((size_t)(b*MM + m0))*KK;
        __syncthreads();
        {   // load + bn2 + relu + cvt — FULL 128-col row
            const float4* src = (const float4*)(g_f0 + (pixbase + r)*H1) + h*16;
            int wbase = r*68 + h*32;
#pragma unroll
            for (int q = 0; q < 16; q++) {
                float4 v = src[q];
                int c = h*64 + q*4;
                float4 a = *(const float4*)&aff2s[c];
                float4 cc = *(const float4*)&aff2s[H1 + c];
                v.x = fmaxf(fmaf(a.x, v.x, cc.x), 0.f);
                v.y = fmaxf(fmaf(a.y, v.y, cc.y), 0.f);
                v.z = fmaxf(fmaf(a.z, v.z, cc.z), 0.f);
                v.w = fmaxf(fmaf(a.w, v.w, cc.w), 0.f);
                Ah2[wbase + 2*q]     = __floats2half2_rn(v.x, v.y);
                Ah2[wbase + 2*q + 1] = __floats2half2_rn(v.z, v.w);
            }
        }
        __syncthreads();

        float acc[2][4][4];
#pragma unroll
        for (int mi = 0; mi < 2; mi++)
#pragma unroll
            for (int ni = 0; ni < 4; ni++) {
                acc[mi][ni][0] = bias0[ni]; acc[mi][ni][1] = bias1[ni];
                acc[mi][ni][2] = bias0[ni]; acc[mi][ni][3] = bias1[ni];
            }
#pragma unroll
        for (int ks = 0; ks < 8; ks++) {
            int kw = ks*8;
            unsigned af[2][4], bf[4][2];
#pragma unroll
            for (int mi = 0; mi < 2; mi++) {
                int rr = warp_pix + mi*16 + g;
                af[mi][0] = Aw[rr*68 + t + kw];
                af[mi][1] = Aw[(rr+8)*68 + t + kw];
                af[mi][2] = Aw[rr*68 + t + 4 + kw];
                af[mi][3] = Aw[(rr+8)*68 + t + 4 + kw];
            }
#pragma unroll
            for (int ni = 0; ni < 4; ni++) {
                int nn = warp_n + ni*8 + g;
                bf[ni][0] = Bw[nn*68 + t + kw];
                bf[ni][1] = Bw[nn*68 + t + 4 + kw];
            }
#pragma unroll
            for (int mi = 0; mi < 2; mi++)
#pragma unroll
                for (int ni = 0; ni < 4; ni++)
                    mma16816(acc[mi][ni], af[mi], bf[ni]);
        }

        // logits partial: s(pix) = sum_j wq2[j] * relu(q_j)
        float* sl = (wid < 4) ? slog0 : slog1;
#pragma unroll
        for (int mi = 0; mi < 2; mi++) {
            float p0 = 0.f, p1 = 0.f;
#pragma unroll
            for (int ni = 0; ni < 4; ni++) {
                float* a = acc[mi][ni];
                p0 = fmaf(w20[ni], fmaxf(a[0], 0.f), p0);
                p0 = fmaf(w21[ni], fmaxf(a[1], 0.f), p0);
                p1 = fmaf(w20[ni], fmaxf(a[2], 0.f), p1);
                p1 = fmaf(w21[ni], fmaxf(a[3], 0.f), p1);
            }
            p0 += __shfl_xor_sync(FULLMASK, p0, 1);
            p0 += __shfl_xor_sync(FULLMASK, p0, 2);
            p1 += __shfl_xor_sync(FULLMASK, p1, 1);
            p1 += __shfl_xor_sync(FULLMASK, p1, 2);
            if (t == 0) {
                sl[warp_pix + mi*16 + g]     = p0;
                sl[warp_pix + mi*16 + 8 + g] = p1;
            }
        }
        __syncthreads();
        if (wid < 4) {   // softmax per m (32 neighbors), bq2 dropped (shift-invariant)
            int idx = wid*32 + lane;
            float s = slog0[idx] + slog1[idx];
            float mx = s;
#pragma unroll
            for (int off = 16; off; off >>= 1)
                mx = fmaxf(mx, __shfl_xor_sync(FULLMASK, mx, off));
            float e = expf(s - mx);
            float sum = e;
#pragma unroll
            for (int off = 16; off; off >>= 1)
                sum += __shfl_xor_sync(FULLMASK, sum, off);
            wk[idx] = e / sum;
        }
        __syncthreads();
        {   // fp32 aggregate: recompute bn2+relu from g_f0 (L2-hot, coalesced over o)
            int o = tid & 127, mh = tid >> 7;
            float a2v = aff2s[o], c2v = aff2s[H1 + o];
#pragma unroll
            for (int mm0 = 0; mm0 < 2; mm0++) {
                int mm = mh + mm0*2;
                const float* src = g_f0 + (pixbase + mm*32)*H1 + o;
                float a = 0.f;
#pragma unroll
                for (int kn = 0; kn < 32; kn++) {
                    float v = fmaxf(fmaf(a2v, src[(size_t)kn*H1], c2v), 0.f);
                    a = fmaf(v, wk[mm*32 + kn], a);
                }
                out[obase + (size_t)o*MM + (m0 + mm)] = a;
            }
        }
        __syncthreads();
    }
}

// ---------------- launch ----------------
extern "C" void kernel_launch(void* const* d_in, const int* in_sizes, int n_in,
                              void* d_out, int out_size) {
    const float* xyz  = (const float*)d_in[0];
    const float* feats= (const float*)d_in[1];
    const float* W1   = (const float*)d_in[2];
    const float* b1   = (const float*)d_in[3];
    const float* g1   = (const float*)d_in[4];
    const float* be1  = (const float*)d_in[5];
    const float* W2   = (const float*)d_in[6];
    const float* b2   = (const float*)d_in[7];
    const float* g2   = (const float*)d_in[8];
    const float* be2  = (const float*)d_in[9];
    const float* Wq1  = (const float*)d_in[10];
    const float* bq1  = (const float*)d_in[11];
    const float* Wq2  = (const float*)d_in[12];
    const float* bq2  = (const float*)d_in[13];
    float* out = (float*)d_out;

    void *s1, *s2, *idxp, *aff1p, *aff2p;
    cudaGetSymbolAddress(&s1, g_stats1);
    cudaGetSymbolAddress(&s2, g_stats2);
    cudaGetSymbolAddress(&idxp, g_idx);
    cudaGetSymbolAddress(&aff1p, g_aff1);
    cudaGetSymbolAddress(&aff2p, g_aff2);

    const int smem1 = 2*128*88*2;                                     // 45056 B
    const int smem2 = 2*128*136*2 + 2*H1*4;                           // 70656 B
    const int smem3 = (128*136 + 64*136)*2 + (2*H1 + 2*Q1 + 3*128)*4; // 55296 B

    cudaFuncSetAttribute(k_gemm1, cudaFuncAttributeMaxDynamicSharedMemorySize, smem1);
    cudaFuncSetAttribute(k_gemm2, cudaFuncAttributeMaxDynamicSharedMemorySize, smem2);
    cudaFuncSetAttribute(k_final, cudaFuncAttributeMaxDynamicSharedMemorySize, smem3);

    cudaMemsetAsync(s1, 0, 2*H1*sizeof(float));
    cudaMemsetAsync(s2, 0, 2*H1*sizeof(float));

    k_pre<<<(BB*PP + 255)/256, 256>>>(feats);
    k_centers<<<(BB*MM + 255)/256, 256>>>(xyz, out);
    k_knn<<<BB*MM/8, 256>>>(xyz, out, (int*)idxp);
    k_gemm1<<<BB*MM/16, 256, smem1>>>(xyz, out, W1, b1);
    k_aff<<<1, H1>>>(g1, be1, (const float*)s1, (float*)aff1p);
    k_gemm2<<<BB*MM/16, 256, smem2>>>(W2, b2);
    k_aff<<<1, H1>>>(g2, be2, (const float*)s2, (float*)aff2p);
    k_final<<<BB*MM/16, 256, smem3>>>(Wq1, bq1, Wq2, bq2, out);
}

// round 8
// speedup vs baseline: 3.1826x; 1.1473x over previous
#include <cuda_runtime.h>
#include <cuda_fp16.h>
#include <math.h>
#include <float.h>

#define BB 4
#define PP 8192
#define CC 64
#define MM 2048
#define KK 32
#define CIN 67
#define H1 128
#define Q1 64
#define NPIX (BB*MM*KK)
#define BN_EPS 1e-5f
#define FULLMASK 0xffffffffu

// ---------------- scratch (fp16 intermediates) ----------------
__device__ __half g_featsT[(size_t)BB*PP*CC];       // (B,P,C) fp16
__device__ int    g_idx[(size_t)BB*MM*KK];
__device__ __half g_h0[(size_t)NPIX*H1];            // [pix][o] fp16 (pre-BN)
__device__ __half g_f0[(size_t)NPIX*H1];            // [pix][o] fp16 (pre-BN)
__device__ float  g_stats1[2*H1];
__device__ float  g_stats2[2*H1];
__device__ float  g_aff1[2*H1];
__device__ float  g_aff2[2*H1];

// ---------------- helpers ----------------
__device__ __forceinline__ void mma16816(float* c, const unsigned* a, const unsigned* b) {
    asm volatile(
        "mma.sync.aligned.m16n8k16.row.col.f32.f16.f16.f32 "
        "{%0,%1,%2,%3}, {%4,%5,%6,%7}, {%8,%9}, {%0,%1,%2,%3};"
        : "+f"(c[0]), "+f"(c[1]), "+f"(c[2]), "+f"(c[3])
        : "r"(a[0]), "r"(a[1]), "r"(a[2]), "r"(a[3]), "r"(b[0]), "r"(b[1]));
}
__device__ __forceinline__ void cp16(unsigned dst, const void* src) {
    asm volatile("cp.async.ca.shared.global [%0], [%1], 16;\n" :: "r"(dst), "l"(src));
}
#define CP_COMMIT() asm volatile("cp.async.commit_group;\n" ::: "memory")
#define CP_WAIT(n)  asm volatile("cp.async.wait_group %0;\n" :: "n"(n) : "memory")

// ---------------- feats transpose + fp16 cvt ----------------
__global__ void k_pre(const float* __restrict__ feats) {
    int gp = blockIdx.x * blockDim.x + threadIdx.x;
    if (gp >= BB*PP) return;
    int b = gp / PP, p = gp % PP;
    const float* src = feats + (size_t)b*CC*PP + p;
    __half2* dst = (__half2*)(g_featsT + (size_t)gp*CC);
#pragma unroll
    for (int c0 = 0; c0 < CC; c0 += 2)
        dst[c0 >> 1] = __floats2half2_rn(src[(size_t)c0*PP], src[(size_t)(c0+1)*PP]);
}

// ---------------- centers (exact jax linspace) ----------------
__global__ void k_centers(const float* __restrict__ xyz, float* __restrict__ out) {
    int i = blockIdx.x * blockDim.x + threadIdx.x;
    if (i >= BB*MM) return;
    int b = i / MM, m = i % MM;
    int pc;
    if (m == MM-1) pc = PP-1;
    else {
        float t = __fdiv_rn((float)m, (float)(MM-1));
        float v = __fmul_rn((float)(PP-1), t);
        pc = (int)v;
        if (pc > PP-1) pc = PP-1;
    }
    const float* s = xyz + ((size_t)(b*PP + pc))*3;
    out[(size_t)i*3 + 0] = s[0];
    out[(size_t)i*3 + 1] = s[1];
    out[(size_t)i*3 + 2] = s[2];
}

// ---------------- KNN: 2 centers per warp ----------------
__global__ void __launch_bounds__(256) k_knn(const float* __restrict__ xyz,
                                             const float* __restrict__ centers,
                                             int* __restrict__ idxout) {
    int c0   = (blockIdx.x * 8 + (threadIdx.x >> 5)) * 2;   // first of 2 centers
    int lane = threadIdx.x & 31;
    int b    = c0 >> 11;
    float cx[2], cy[2], cz[2], cc2[2];
#pragma unroll
    for (int jj = 0; jj < 2; jj++) {
        const float* cp = centers + (size_t)(c0 + jj)*3;
        cx[jj] = cp[0]; cy[jj] = cp[1]; cz[jj] = cp[2];
        cc2[jj] = cx[jj]*cx[jj] + cy[jj]*cy[jj] + cz[jj]*cz[jj];
    }
    const float* xb = xyz + (size_t)b*PP*3;

    float ld[2] = {FLT_MAX, FLT_MAX};
    int   li[2] = {0x7fffffff, 0x7fffffff};
    float kth[2] = {FLT_MAX, FLT_MAX};

    for (int base = 0; base < PP; base += 32) {
        int p = base + lane;
        float x = xb[3*p], y = xb[3*p+1], z = xb[3*p+2];
        float x2 = x*x + y*y + z*z;
#pragma unroll
        for (int jj = 0; jj < 2; jj++) {
            float d = (cc2[jj] + x2) - 2.0f*(cx[jj]*x + cy[jj]*y + cz[jj]*z);
            unsigned mask = __ballot_sync(FULLMASK, d < kth[jj]);
            while (mask) {
                int j = __ffs(mask) - 1; mask &= mask - 1;
                float dj = __shfl_sync(FULLMASK, d, j);
                if (dj < kth[jj]) {
                    int pj = base + j;
                    unsigned lt = __ballot_sync(FULLMASK,
                        (ld[jj] < dj) || (ld[jj] == dj && li[jj] < pj));
                    int pos = __popc(lt);
                    float pd = __shfl_up_sync(FULLMASK, ld[jj], 1);
                    int   pi = __shfl_up_sync(FULLMASK, li[jj], 1);
                    if (lane == pos)      { ld[jj] = dj; li[jj] = pj; }
                    else if (lane > pos)  { ld[jj] = pd; li[jj] = pi; }
                    kth[jj] = __shfl_sync(FULLMASK, ld[jj], 31);
                }
            }
        }
    }
#pragma unroll
    for (int jj = 0; jj < 2; jj++)
        idxout[(size_t)(c0 + jj)*KK + lane] = li[jj];
}

// ================= GEMM1: cp.async double-buffered gather + MMA =================
// A bufs: 2 x 128 rows x 88 halfs (176B rows, 16B aligned). B: 128 x 88 halfs.
__global__ void __launch_bounds__(256, 2) k_gemm1(const float* __restrict__ xyz,
                                                  const float* __restrict__ centers,
                                                  const float* __restrict__ W1,
                                                  const float* __restrict__ b1) {
    extern __shared__ __half sh[];
    __half* Ab = sh;                       // 2 * 128*88
    __half* Bs = sh + 2*128*88;
    unsigned* Bw = (unsigned*)Bs;

    int tid = threadIdx.x, wid = tid >> 5, lane = tid & 31;
    int g = lane >> 2, t = lane & 3;
    int warp_pix = (wid >> 2) * 64, warp_n = (wid & 3) * 32;
    int r = tid >> 1, h = tid & 1;

    // B zero + fill
    for (int i = tid; i < 128*44; i += 256) Bw[i] = 0u;
    // A pad cols 64..87 zero (64..67 rewritten per tile; 68..79 read as zero by MMA)
    {
        __half z = __float2half_rn(0.f);
#pragma unroll
        for (int bufi = 0; bufi < 2; bufi++)
            if (h == 1)
                for (int q = 64; q < 88; q++) Ab[bufi*128*88 + r*88 + q] = z;
    }
    __syncthreads();
    for (int i = tid; i < H1*CIN; i += 256) {
        int o = i / CIN, c = i - o*CIN;
        int col = (c < 3) ? (64 + c) : (c - 3);
        Bs[o*88 + col] = __float2half_rn(W1[i]);
    }
    float bias0[4], bias1[4];
#pragma unroll
    for (int ni = 0; ni < 4; ni++) {
        bias0[ni] = b1[warp_n + ni*8 + 2*t];
        bias1[ni] = b1[warp_n + ni*8 + 2*t + 1];
    }

    int b      = blockIdx.x / (MM/16);
    int m_base = (blockIdx.x % (MM/16)) * 16;
    unsigned abase = (unsigned)__cvta_generic_to_shared(Ab);

    float ss[4][2], sq[4][2];
#pragma unroll
    for (int ni = 0; ni < 4; ni++) { ss[ni][0]=ss[ni][1]=0.f; sq[ni][0]=sq[ni][1]=0.f; }

    auto stage = [&](int tile, int bufi) {
        int m0 = m_base + tile*4;
        size_t pixbase = ((size_t)(b*MM + m0))*KK;
        int p = g_idx[pixbase + r];
        const char* srcp = (const char*)(g_featsT + ((size_t)(b*PP + p))*CC) + h*64;
        unsigned sdst = abase + (unsigned)(bufi*128*88 + r*88)*2 + h*64;
#pragma unroll
        for (int q = 0; q < 4; q++) cp16(sdst + q*16, srcp + q*16);
        if (h == 0) {
            int m = m0 + (r >> 5);
            const float* xp = xyz + ((size_t)(b*PP + p))*3;
            const float* cpt = centers + ((size_t)(b*MM + m))*3;
            __half2* A2 = (__half2*)(Ab + bufi*128*88);
            A2[r*44 + 32] = __floats2half2_rn(xp[0]-cpt[0], xp[1]-cpt[1]);
            A2[r*44 + 33] = __floats2half2_rn(xp[2]-cpt[2], 0.f);
        }
        CP_COMMIT();
    };

    stage(0, 0);
    for (int tile = 0; tile < 4; tile++) {
        if (tile < 3) stage(tile+1, (tile+1)&1);
        if (tile < 3) CP_WAIT(1); else CP_WAIT(0);
        __syncthreads();

        const unsigned* Aw = (const unsigned*)(Ab + (tile&1)*128*88);
        size_t pixbase = ((size_t)(b*MM + m_base + tile*4))*KK;

        float acc[4][4][4];
#pragma unroll
        for (int mi = 0; mi < 4; mi++)
#pragma unroll
            for (int ni = 0; ni < 4; ni++) {
                acc[mi][ni][0] = bias0[ni]; acc[mi][ni][1] = bias1[ni];
                acc[mi][ni][2] = bias0[ni]; acc[mi][ni][3] = bias1[ni];
            }
#pragma unroll
        for (int ks = 0; ks < 5; ks++) {
            int kw = ks*8;
            unsigned af[4][4], bf[4][2];
#pragma unroll
            for (int mi = 0; mi < 4; mi++) {
                int rr = warp_pix + mi*16 + g;
                af[mi][0] = Aw[rr*44 + t + kw];
                af[mi][1] = Aw[(rr+8)*44 + t + kw];
                af[mi][2] = Aw[rr*44 + t + 4 + kw];
                af[mi][3] = Aw[(rr+8)*44 + t + 4 + kw];
            }
#pragma unroll
            for (int ni = 0; ni < 4; ni++) {
                int nn = warp_n + ni*8 + g;
                bf[ni][0] = Bw[nn*44 + t + kw];
                bf[ni][1] = Bw[nn*44 + t + 4 + kw];
            }
#pragma unroll
            for (int mi = 0; mi < 4; mi++)
#pragma unroll
                for (int ni = 0; ni < 4; ni++)
                    mma16816(acc[mi][ni], af[mi], bf[ni]);
        }
#pragma unroll
        for (int mi = 0; mi < 4; mi++) {
            int row = warp_pix + mi*16 + g;
#pragma unroll
            for (int ni = 0; ni < 4; ni++) {
                int col = warp_n + ni*8 + 2*t;
                float* a = acc[mi][ni];
                *(__half2*)&g_h0[(pixbase + row)*H1 + col]     = __floats2half2_rn(a[0], a[1]);
                *(__half2*)&g_h0[(pixbase + row + 8)*H1 + col] = __floats2half2_rn(a[2], a[3]);
                ss[ni][0] += a[0] + a[2];  ss[ni][1] += a[1] + a[3];
                sq[ni][0] += a[0]*a[0] + a[2]*a[2];
                sq[ni][1] += a[1]*a[1] + a[3]*a[3];
            }
        }
        __syncthreads();
    }
#pragma unroll
    for (int ni = 0; ni < 4; ni++)
#pragma unroll
        for (int j = 0; j < 2; j++) {
            float s = ss[ni][j], q = sq[ni][j];
            s += __shfl_xor_sync(FULLMASK, s, 4);  q += __shfl_xor_sync(FULLMASK, q, 4);
            s += __shfl_xor_sync(FULLMASK, s, 8);  q += __shfl_xor_sync(FULLMASK, q, 8);
            s += __shfl_xor_sync(FULLMASK, s, 16); q += __shfl_xor_sync(FULLMASK, q, 16);
            if (g == 0) {
                int o = warp_n + ni*8 + 2*t + j;
                atomicAdd(&g_stats1[o], s);
                atomicAdd(&g_stats1[H1 + o], q);
            }
        }
}

// ---------------- BN affine (stats from fp32 accumulators — exact) ----------------
__global__ void k_aff(const float* __restrict__ gg, const float* __restrict__ be,
                      const float* __restrict__ stats, float* __restrict__ aff) {
    int o = threadIdx.x;
    float inv = 1.0f / (float)NPIX;
    float mean = stats[o] * inv;
    float var  = stats[H1 + o] * inv - mean*mean;
    float a = gg[o] * rsqrtf(var + BN_EPS);
    aff[o] = a;
    aff[H1 + o] = be[o] - a*mean;
}

// ================= GEMM2: relu(bn1(h0 fp16)) x W2^T =================
__global__ void __launch_bounds__(256, 2) k_gemm2(const float* __restrict__ W2,
                                                  const float* __restrict__ b2) {
    extern __shared__ __half sh[];
    __half* As = sh;                  // 128*136
    __half* Bs = sh + 128*136;
    float* aff1s = (float*)(sh + 2*128*136);
    unsigned* Aw = (unsigned*)As;
    unsigned* Bw = (unsigned*)Bs;
    __half2* Ah2 = (__half2*)As;
    __half2* Bh2 = (__half2*)Bs;

    int tid = threadIdx.x, wid = tid >> 5, lane = tid & 31;
    int g = lane >> 2, t = lane & 3;
    int warp_pix = (wid >> 2) * 64, warp_n = (wid & 3) * 32;
    int r = tid >> 1, h = tid & 1;

    for (int i = tid; i < H1*64; i += 256) {
        int o = i >> 6, wp = i & 63;
        float2 v = ((const float2*)W2)[o*64 + wp];
        Bh2[o*68 + wp] = __floats2half2_rn(v.x, v.y);
    }
    for (int i = tid; i < 2*H1; i += 256) aff1s[i] = g_aff1[i];
    float bias0[4], bias1[4];
#pragma unroll
    for (int ni = 0; ni < 4; ni++) {
        bias0[ni] = b2[warp_n + ni*8 + 2*t];
        bias1[ni] = b2[warp_n + ni*8 + 2*t + 1];
    }

    int b      = blockIdx.x / (MM/16);
    int m_base = (blockIdx.x % (MM/16)) * 16;

    float ss[4][2], sq[4][2];
#pragma unroll
    for (int ni = 0; ni < 4; ni++) { ss[ni][0]=ss[ni][1]=0.f; sq[ni][0]=sq[ni][1]=0.f; }

    for (int tile = 0; tile < 4; tile++) {
        size_t pixbase = ((size_t)(b*MM + m_base + tile*4))*KK;
        __syncthreads();
        {   // load fp16 h0, bn1+relu in fp32, repack fp16 — FULL row
            const uint4* src = (const uint4*)(g_h0 + (pixbase + r)*H1) + h*8;
            int wbase = r*68 + h*32;   // half2 units
#pragma unroll
            for (int q = 0; q < 8; q++) {
                uint4 v = src[q];
                int c = h*64 + q*8;
                const __half2* hv = (const __half2*)&v;
#pragma unroll
                for (int i2 = 0; i2 < 4; i2++) {
                    float2 f = __half22float2(hv[i2]);
                    float2 a = *(const float2*)&aff1s[c + 2*i2];
                    float2 cc = *(const float2*)&aff1s[H1 + c + 2*i2];
                    f.x = fmaxf(fmaf(a.x, f.x, cc.x), 0.f);
                    f.y = fmaxf(fmaf(a.y, f.y, cc.y), 0.f);
                    Ah2[wbase + q*4 + i2] = __floats2half2_rn(f.x, f.y);
                }
            }
        }
        __syncthreads();

        float acc[4][4][4];
#pragma unroll
        for (int mi = 0; mi < 4; mi++)
#pragma unroll
            for (int ni = 0; ni < 4; ni++) {
                acc[mi][ni][0] = bias0[ni]; acc[mi][ni][1] = bias1[ni];
                acc[mi][ni][2] = bias0[ni]; acc[mi][ni][3] = bias1[ni];
            }
#pragma unroll
        for (int ks = 0; ks < 8; ks++) {
            int kw = ks*8;
            unsigned af[4][4], bf[4][2];
#pragma unroll
            for (int mi = 0; mi < 4; mi++) {
                int rr = warp_pix + mi*16 + g;
                af[mi][0] = Aw[rr*68 + t + kw];
                af[mi][1] = Aw[(rr+8)*68 + t + kw];
                af[mi][2] = Aw[rr*68 + t + 4 + kw];
                af[mi][3] = Aw[(rr+8)*68 + t + 4 + kw];
            }
#pragma unroll
            for (int ni = 0; ni < 4; ni++) {
                int nn = warp_n + ni*8 + g;
                bf[ni][0] = Bw[nn*68 + t + kw];
                bf[ni][1] = Bw[nn*68 + t + 4 + kw];
            }
#pragma unroll
            for (int mi = 0; mi < 4; mi++)
#pragma unroll
                for (int ni = 0; ni < 4; ni++)
                    mma16816(acc[mi][ni], af[mi], bf[ni]);
        }
#pragma unroll
        for (int mi = 0; mi < 4; mi++) {
            int row = warp_pix + mi*16 + g;
#pragma unroll
            for (int ni = 0; ni < 4; ni++) {
                int col = warp_n + ni*8 + 2*t;
                float* a = acc[mi][ni];
                *(__half2*)&g_f0[(pixbase + row)*H1 + col]     = __floats2half2_rn(a[0], a[1]);
                *(__half2*)&g_f0[(pixbase + row + 8)*H1 + col] = __floats2half2_rn(a[2], a[3]);
                ss[ni][0] += a[0] + a[2];  ss[ni][1] += a[1] + a[3];
                sq[ni][0] += a[0]*a[0] + a[2]*a[2];
                sq[ni][1] += a[1]*a[1] + a[3]*a[3];
            }
        }
    }
#pragma unroll
    for (int ni = 0; ni < 4; ni++)
#pragma unroll
        for (int j = 0; j < 2; j++) {
            float s = ss[ni][j], q = sq[ni][j];
            s += __shfl_xor_sync(FULLMASK, s, 4);  q += __shfl_xor_sync(FULLMASK, q, 4);
            s += __shfl_xor_sync(FULLMASK, s, 8);  q += __shfl_xor_sync(FULLMASK, q, 8);
            s += __shfl_xor_sync(FULLMASK, s, 16); q += __shfl_xor_sync(FULLMASK, q, 16);
            if (g == 0) {
                int o = warp_n + ni*8 + 2*t + j;
                atomicAdd(&g_stats2[o], s);
                atomicAdd(&g_stats2[H1 + o], q);
            }
        }
}

// ================= final: bn2+relu, q-GEMM, softmax, aggregate from smem ====
__global__ void __launch_bounds__(256, 2) k_final(const float* __restrict__ Wq1,
                                                  const float* __restrict__ bq1,
                                                  const float* __restrict__ Wq2,
                                                  const float* __restrict__ bq2,
                                                  float* __restrict__ out) {
    extern __shared__ __half sh[];
    __half* As = sh;                  // 128*136
    __half* Bs = sh + 128*136;        // 64*136
    float* aff2s = (float*)(sh + 128*136 + 64*136);
    float* bq1s  = aff2s + 2*H1;
    float* wq2s  = bq1s + Q1;
    float* slog0 = wq2s + Q1;
    float* slog1 = slog0 + 128;
    float* wk    = slog1 + 128;
    unsigned* Aw = (unsigned*)As;
    unsigned* Bw = (unsigned*)Bs;
    __half2* Ah2 = (__half2*)As;
    __half2* Bh2 = (__half2*)Bs;

    int tid = threadIdx.x, wid = tid >> 5, lane = tid & 31;
    int g = lane >> 2, t = lane & 3;
    int warp_pix = (wid & 3) * 32, warp_n = (wid >> 2) * 32;
    int r = tid >> 1, h = tid & 1;

    for (int i = tid; i < Q1*64; i += 256) {
        int n = i >> 6, wp = i & 63;
        float2 v = ((const float2*)Wq1)[n*64 + wp];
        Bh2[n*68 + wp] = __floats2half2_rn(v.x, v.y);
    }
    for (int i = tid; i < 2*H1; i += 256) aff2s[i] = g_aff2[i];
    if (tid < Q1) { bq1s[tid] = bq1[tid]; wq2s[tid] = Wq2[tid]; }

    float bias0[4], bias1[4], w20[4], w21[4];
    __syncthreads();
#pragma unroll
    for (int ni = 0; ni < 4; ni++) {
        bias0[ni] = bq1s[warp_n + ni*8 + 2*t];
        bias1[ni] = bq1s[warp_n + ni*8 + 2*t + 1];
        w20[ni]   = wq2s[warp_n + ni*8 + 2*t];
        w21[ni]   = wq2s[warp_n + ni*8 + 2*t + 1];
    }

    int b      = blockIdx.x / (MM/16);
    int m_base = (blockIdx.x % (MM/16)) * 16;
    size_t obase = (size_t)BB*MM*3 + (size_t)b*H1*MM;

    for (int tile = 0; tile < 4; tile++) {
        int m0 = m_base + tile*4;
        size_t pixbase = ((size_t)(b*MM + m0))*KK;
        __syncthreads();
        {   // load fp16 f0, bn2+relu fp32 math, repack fp16
            const uint4* src = (const uint4*)(g_f0 + (pixbase + r)*H1) + h*8;
            int wbase = r*68 + h*32;
#pragma unroll
            for (int q = 0; q < 8; q++) {
                uint4 v = src[q];
                int c = h*64 + q*8;
                const __half2* hv = (const __half2*)&v;
#pragma unroll
                for (int i2 = 0; i2 < 4; i2++) {
                    float2 f = __half22float2(hv[i2]);
                    float2 a = *(const float2*)&aff2s[c + 2*i2];
                    float2 cc = *(const float2*)&aff2s[H1 + c + 2*i2];
                    f.x = fmaxf(fmaf(a.x, f.x, cc.x), 0.f);
                    f.y = fmaxf(fmaf(a.y, f.y, cc.y), 0.f);
                    Ah2[wbase + q*4 + i2] = __floats2half2_rn(f.x, f.y);
                }
            }
        }
        __syncthreads();

        float acc[2][4][4];
#pragma unroll
        for (int mi = 0; mi < 2; mi++)
#pragma unroll
            for (int ni = 0; ni < 4; ni++) {
                acc[mi][ni][0] = bias0[ni]; acc[mi][ni][1] = bias1[ni];
                acc[mi][ni][2] = bias0[ni]; acc[mi][ni][3] = bias1[ni];
            }
#pragma unroll
        for (int ks = 0; ks < 8; ks++) {
            int kw = ks*8;
            unsigned af[2][4], bf[4][2];
#pragma unroll
            for (int mi = 0; mi < 2; mi++) {
                int rr = warp_pix + mi*16 + g;
                af[mi][0] = Aw[rr*68 + t + kw];
                af[mi][1] = Aw[(rr+8)*68 + t + kw];
                af[mi][2] = Aw[rr*68 + t + 4 + kw];
                af[mi][3] = Aw[(rr+8)*68 + t + 4 + kw];
            }
#pragma unroll
            for (int ni = 0; ni < 4; ni++) {
                int nn = warp_n + ni*8 + g;
                bf[ni][0] = Bw[nn*68 + t + kw];
                bf[ni][1] = Bw[nn*68 + t + 4 + kw];
            }
#pragma unroll
            for (int mi = 0; mi < 2; mi++)
#pragma unroll
                for (int ni = 0; ni < 4; ni++)
                    mma16816(acc[mi][ni], af[mi], bf[ni]);
        }

        // logits partial: s(pix) = sum_j wq2[j] * relu(q_j)
        float* sl = (wid < 4) ? slog0 : slog1;
#pragma unroll
        for (int mi = 0; mi < 2; mi++) {
            float p0 = 0.f, p1 = 0.f;
#pragma unroll
            for (int ni = 0; ni < 4; ni++) {
                float* a = acc[mi][ni];
                p0 = fmaf(w20[ni], fmaxf(a[0], 0.f), p0);
                p0 = fmaf(w21[ni], fmaxf(a[1], 0.f), p0);
                p1 = fmaf(w20[ni], fmaxf(a[2], 0.f), p1);
                p1 = fmaf(w21[ni], fmaxf(a[3], 0.f), p1);
            }
            p0 += __shfl_xor_sync(FULLMASK, p0, 1);
            p0 += __shfl_xor_sync(FULLMASK, p0, 2);
            p1 += __shfl_xor_sync(FULLMASK, p1, 1);
            p1 += __shfl_xor_sync(FULLMASK, p1, 2);
            if (t == 0) {
                sl[warp_pix + mi*16 + g]     = p0;
                sl[warp_pix + mi*16 + 8 + g] = p1;
            }
        }
        __syncthreads();
        if (wid < 4) {   // softmax per m over 32 neighbors (bq2 shift-invariant)
            int idx = wid*32 + lane;
            float s = slog0[idx] + slog1[idx];
            float mx = s;
#pragma unroll
            for (int off = 16; off; off >>= 1)
                mx = fmaxf(mx, __shfl_xor_sync(FULLMASK, mx, off));
            float e = expf(s - mx);
            float sum = e;
#pragma unroll
            for (int off = 16; off; off >>= 1)
                sum += __shfl_xor_sync(FULLMASK, sum, off);
            wk[idx] = e / sum;
        }
        __syncthreads();
        {   // aggregate from smem A-tile (fp16 feat_local, fp32 accumulate)
            int o = tid & 127, mh = tid >> 7;
#pragma unroll
            for (int mm0 = 0; mm0 < 2; mm0++) {
                int mm = mh + mm0*2;
                float a = 0.f;
#pragma unroll
                for (int kn = 0; kn < 32; kn++)
                    a = fmaf(__half2float(As[(mm*32 + kn)*136 + o]), wk[mm*32 + kn], a);
                out[obase + (size_t)o*MM + (m0 + mm)] = a;
            }
        }
        __syncthreads();
    }
}

// ---------------- launch ----------------
extern "C" void kernel_launch(void* const* d_in, const int* in_sizes, int n_in,
                              void* d_out, int out_size) {
    const float* xyz  = (const float*)d_in[0];
    const float* feats= (const float*)d_in[1];
    const float* W1   = (const float*)d_in[2];
    const float* b1   = (const float*)d_in[3];
    const float* g1   = (const float*)d_in[4];
    const float* be1  = (const float*)d_in[5];
    const float* W2   = (const float*)d_in[6];
    const float* b2   = (const float*)d_in[7];
    const float* g2   = (const float*)d_in[8];
    const float* be2  = (const float*)d_in[9];
    const float* Wq1  = (const float*)d_in[10];
    const float* bq1  = (const float*)d_in[11];
    const float* Wq2  = (const float*)d_in[12];
    const float* bq2  = (const float*)d_in[13];
    float* out = (float*)d_out;

    void *s1, *s2, *idxp, *aff1p, *aff2p;
    cudaGetSymbolAddress(&s1, g_stats1);
    cudaGetSymbolAddress(&s2, g_stats2);
    cudaGetSymbolAddress(&idxp, g_idx);
    cudaGetSymbolAddress(&aff1p, g_aff1);
    cudaGetSymbolAddress(&aff2p, g_aff2);

    const int smem1 = (2*128*88 + 128*88)*2;                          // 67584 B
    const int smem2 = 2*128*136*2 + 2*H1*4;                           // 70656 B
    const int smem3 = (128*136 + 64*136)*2 + (2*H1 + 2*Q1 + 3*128)*4; // 55296 B

    cudaFuncSetAttribute(k_gemm1, cudaFuncAttributeMaxDynamicSharedMemorySize, smem1);
    cudaFuncSetAttribute(k_gemm2, cudaFuncAttributeMaxDynamicSharedMemorySize, smem2);
    cudaFuncSetAttribute(k_final, cudaFuncAttributeMaxDynamicSharedMemorySize, smem3);

    cudaMemsetAsync(s1, 0, 2*H1*sizeof(float));
    cudaMemsetAsync(s2, 0, 2*H1*sizeof(float));

    k_pre<<<(BB*PP + 255)/256, 256>>>(feats);
    k_centers<<<(BB*MM + 255)/256, 256>>>(xyz, out);
    k_knn<<<BB*MM/16, 256>>>(xyz, out, (int*)idxp);
    k_gemm1<<<BB*MM/16, 256, smem1>>>(xyz, out, W1, b1);
    k_aff<<<1, H1>>>(g1, be1, (const float*)s1, (float*)aff1p);
    k_gemm2<<<BB*MM/16, 256, smem2>>>(W2, b2);
    k_aff<<<1, H1>>>(g2, be2, (const float*)s2, (float*)aff2p);
    k_final<<<BB*MM/16, 256, smem3>>>(Wq1, bq1, Wq2, bq2, out);
}